// round 2
// baseline (speedup 1.0000x reference)
#include <cuda_runtime.h>
#include <math.h>

// Problem constants
#define NT 4096      // tokens (2*2048)
#define DM 1024      // d_model
#define NH 4096      // hidden
#define NE 8         // experts
#define NSLOTS (NT * 2)  // total (token, expert) pairs = T * TOP_K

// -------- device scratch (no allocations allowed) --------
__device__ float g_combine[NT * NE];            // per-token per-expert weight (0 if unselected)
__device__ int   g_list[NE * NT];               // token ids per expert
__device__ int   g_count[NE];                   // tokens per expert
__device__ int   g_offset[NE + 1];              // exclusive prefix over counts
__device__ float g_hbuf[(size_t)NSLOTS * NH];   // gated hidden activations, 134 MB

// ---------------------------------------------------------
// Kernel 0: zero output + reset counters
// ---------------------------------------------------------
__global__ void zero_kernel(float* __restrict__ out, int n) {
    int i = blockIdx.x * blockDim.x + threadIdx.x;
    if (i < n) out[i] = 0.0f;
    if (blockIdx.x == 0 && threadIdx.x < NE) g_count[threadIdx.x] = 0;
}

// ---------------------------------------------------------
// Kernel 1: router. One warp per token.
// logits = x[t] @ Wr  -> top2 -> combine weights = renormalized softmax probs
// w1 = p1/(p1+p2) = sigmoid(l1 - l2)  (full softmax denominator cancels)
// ---------------------------------------------------------
__global__ void router_kernel(const float* __restrict__ x,
                              const float* __restrict__ Wr) {
    int warp = (blockIdx.x * blockDim.x + threadIdx.x) >> 5;
    int lane = threadIdx.x & 31;
    if (warp >= NT) return;

    const float* xr = x + (size_t)warp * DM;
    float acc[NE];
#pragma unroll
    for (int e = 0; e < NE; e++) acc[e] = 0.0f;

    for (int d = lane; d < DM; d += 32) {
        float xv = xr[d];
        const float4* w4 = reinterpret_cast<const float4*>(Wr + (size_t)d * NE);
        float4 wa = w4[0];
        float4 wb = w4[1];
        acc[0] = fmaf(xv, wa.x, acc[0]);
        acc[1] = fmaf(xv, wa.y, acc[1]);
        acc[2] = fmaf(xv, wa.z, acc[2]);
        acc[3] = fmaf(xv, wa.w, acc[3]);
        acc[4] = fmaf(xv, wb.x, acc[4]);
        acc[5] = fmaf(xv, wb.y, acc[5]);
        acc[6] = fmaf(xv, wb.z, acc[6]);
        acc[7] = fmaf(xv, wb.w, acc[7]);
    }
#pragma unroll
    for (int e = 0; e < NE; e++) {
#pragma unroll
        for (int off = 16; off > 0; off >>= 1)
            acc[e] += __shfl_xor_sync(0xffffffffu, acc[e], off);
    }

    if (lane == 0) {
        // top-2 with lowest-index tie break (matches jax.lax.top_k)
        int e1 = 0;
#pragma unroll
        for (int e = 1; e < NE; e++)
            if (acc[e] > acc[e1]) e1 = e;
        int e2 = (e1 == 0) ? 1 : 0;
#pragma unroll
        for (int e = 0; e < NE; e++) {
            if (e == e1) continue;
            if (acc[e] > acc[e2]) e2 = e;
        }
        float w1 = 1.0f / (1.0f + expf(acc[e2] - acc[e1]));
        float w2 = 1.0f - w1;

        float* crow = g_combine + (size_t)warp * NE;
#pragma unroll
        for (int e = 0; e < NE; e++) crow[e] = 0.0f;
        crow[e1] = w1;
        crow[e2] = w2;

        int p1 = atomicAdd(&g_count[e1], 1);
        g_list[e1 * NT + p1] = warp;
        int p2 = atomicAdd(&g_count[e2], 1);
        g_list[e2 * NT + p2] = warp;
    }
}

// ---------------------------------------------------------
// Kernel 2: 8-wide exclusive prefix sum of counts
// ---------------------------------------------------------
__global__ void prefix_kernel() {
    if (threadIdx.x == 0) {
        int o = 0;
        for (int e = 0; e < NE; e++) {
            g_offset[e] = o;
            o += g_count[e];
        }
        g_offset[NE] = o;
    }
}

// ---------------------------------------------------------
// GEMM tiling config (fp32 SIMT, 64x64x16 tile, 256 threads, 4x4 micro-tile)
// ---------------------------------------------------------
#define TM 64
#define TN 64
#define KB 16

// Kernel 3: per-expert gathered GEMM, fused dual-B (Wg and Wu) + SiLU epilogue.
//   A   = x rows gathered via g_list[e]            [cnt x DM]
//   C1  = A @ Wg[e], C2 = A @ Wu[e]                [cnt x NH]
//   hbuf[slot] = silu(C1) * C2 * combine_weight
__global__ void __launch_bounds__(256)
gemm1_kernel(const float* __restrict__ x,
             const float* __restrict__ Wg,
             const float* __restrict__ Wu) {
    int e   = blockIdx.z;
    int cnt = g_count[e];
    int m0  = blockIdx.y * TM;
    if (m0 >= cnt) return;
    int n0   = blockIdx.x * TN;
    int base = g_offset[e];
    const int* list = g_list + e * NT;
    const float* Bg = Wg + (size_t)e * DM * NH;
    const float* Bu = Wu + (size_t)e * DM * NH;

    __shared__ __align__(16) float As[KB][TM];
    __shared__ __align__(16) float Bs1[KB][TN];
    __shared__ __align__(16) float Bs2[KB][TN];

    int tid = threadIdx.x;
    int tx = tid & 15;   // output col group (4 cols)
    int ty = tid >> 4;   // output row group (4 rows)

    // A load mapping: one float4 per thread: row = tid/4, k-quarter = tid%4
    int arow = tid >> 2;
    int akq  = (tid & 3) * 4;
    const float* aPtr = nullptr;
    if (m0 + arow < cnt) {
        int tok = list[m0 + arow];
        aPtr = x + (size_t)tok * DM;
    }

    // B load mapping: one float4 per thread per matrix: k = tid/16, n-quad = tid%16
    int bk = tid >> 4;
    int bn = (tid & 15) * 4;

    float c1[4][4], c2[4][4];
#pragma unroll
    for (int i = 0; i < 4; i++)
#pragma unroll
        for (int j = 0; j < 4; j++) { c1[i][j] = 0.0f; c2[i][j] = 0.0f; }

    for (int k0 = 0; k0 < DM; k0 += KB) {
        float4 av = make_float4(0.f, 0.f, 0.f, 0.f);
        if (aPtr) av = *reinterpret_cast<const float4*>(aPtr + k0 + akq);
        float4 b1 = *reinterpret_cast<const float4*>(Bg + (size_t)(k0 + bk) * NH + n0 + bn);
        float4 b2 = *reinterpret_cast<const float4*>(Bu + (size_t)(k0 + bk) * NH + n0 + bn);

        __syncthreads();
        As[akq + 0][arow] = av.x;
        As[akq + 1][arow] = av.y;
        As[akq + 2][arow] = av.z;
        As[akq + 3][arow] = av.w;
        *reinterpret_cast<float4*>(&Bs1[bk][bn]) = b1;
        *reinterpret_cast<float4*>(&Bs2[bk][bn]) = b2;
        __syncthreads();

#pragma unroll
        for (int kk = 0; kk < KB; kk++) {
            float4 ta = *reinterpret_cast<const float4*>(&As[kk][ty * 4]);
            float4 t1 = *reinterpret_cast<const float4*>(&Bs1[kk][tx * 4]);
            float4 t2 = *reinterpret_cast<const float4*>(&Bs2[kk][tx * 4]);
            float a[4]  = {ta.x, ta.y, ta.z, ta.w};
            float b1r[4] = {t1.x, t1.y, t1.z, t1.w};
            float b2r[4] = {t2.x, t2.y, t2.z, t2.w};
#pragma unroll
            for (int i = 0; i < 4; i++)
#pragma unroll
                for (int j = 0; j < 4; j++) {
                    c1[i][j] = fmaf(a[i], b1r[j], c1[i][j]);
                    c2[i][j] = fmaf(a[i], b2r[j], c2[i][j]);
                }
        }
    }

    // Epilogue: silu(c1) * c2 * combine weight -> hbuf
#pragma unroll
    for (int i = 0; i < 4; i++) {
        int m = m0 + ty * 4 + i;
        if (m >= cnt) continue;
        int tok = list[m];
        float w = g_combine[(size_t)tok * NE + e];
        float* hrow = g_hbuf + (size_t)(base + m) * NH + n0 + tx * 4;
        float4 o;
        float g0 = c1[i][0], g1 = c1[i][1], g2 = c1[i][2], g3 = c1[i][3];
        o.x = (g0 / (1.0f + expf(-g0))) * c2[i][0] * w;
        o.y = (g1 / (1.0f + expf(-g1))) * c2[i][1] * w;
        o.z = (g2 / (1.0f + expf(-g2))) * c2[i][2] * w;
        o.w = (g3 / (1.0f + expf(-g3))) * c2[i][3] * w;
        *reinterpret_cast<float4*>(hrow) = o;
    }
}

// Kernel 4: per-expert GEMM hbuf @ Wd[e], scatter-add into out.
__global__ void __launch_bounds__(256)
gemm2_kernel(const float* __restrict__ Wd, float* __restrict__ out) {
    int e   = blockIdx.z;
    int cnt = g_count[e];
    int m0  = blockIdx.y * TM;
    if (m0 >= cnt) return;
    int n0   = blockIdx.x * TN;
    int base = g_offset[e];
    const int* list = g_list + e * NT;
    const float* B = Wd + (size_t)e * NH * DM;

    __shared__ __align__(16) float As[KB][TM];
    __shared__ __align__(16) float Bs[KB][TN];

    int tid = threadIdx.x;
    int tx = tid & 15;
    int ty = tid >> 4;

    int arow = tid >> 2;
    int akq  = (tid & 3) * 4;
    const float* aPtr = nullptr;
    if (m0 + arow < cnt)
        aPtr = g_hbuf + (size_t)(base + m0 + arow) * NH;

    int bk = tid >> 4;
    int bn = (tid & 15) * 4;

    float c[4][4];
#pragma unroll
    for (int i = 0; i < 4; i++)
#pragma unroll
        for (int j = 0; j < 4; j++) c[i][j] = 0.0f;

    for (int k0 = 0; k0 < NH; k0 += KB) {
        float4 av = make_float4(0.f, 0.f, 0.f, 0.f);
        if (aPtr) av = *reinterpret_cast<const float4*>(aPtr + k0 + akq);
        float4 bv = *reinterpret_cast<const float4*>(B + (size_t)(k0 + bk) * DM + n0 + bn);

        __syncthreads();
        As[akq + 0][arow] = av.x;
        As[akq + 1][arow] = av.y;
        As[akq + 2][arow] = av.z;
        As[akq + 3][arow] = av.w;
        *reinterpret_cast<float4*>(&Bs[bk][bn]) = bv;
        __syncthreads();

#pragma unroll
        for (int kk = 0; kk < KB; kk++) {
            float4 ta = *reinterpret_cast<const float4*>(&As[kk][ty * 4]);
            float4 tb = *reinterpret_cast<const float4*>(&Bs[kk][tx * 4]);
            float a[4] = {ta.x, ta.y, ta.z, ta.w};
            float b[4] = {tb.x, tb.y, tb.z, tb.w};
#pragma unroll
            for (int i = 0; i < 4; i++)
#pragma unroll
                for (int j = 0; j < 4; j++)
                    c[i][j] = fmaf(a[i], b[j], c[i][j]);
        }
    }

#pragma unroll
    for (int i = 0; i < 4; i++) {
        int m = m0 + ty * 4 + i;
        if (m >= cnt) continue;
        int tok = list[m];
        float* orow = out + (size_t)tok * DM + n0 + tx * 4;
#pragma unroll
        for (int j = 0; j < 4; j++)
            atomicAdd(&orow[j], c[i][j]);
    }
}

// ---------------------------------------------------------
extern "C" void kernel_launch(void* const* d_in, const int* in_sizes, int n_in,
                              void* d_out, int out_size) {
    const float* x  = (const float*)d_in[0];
    const float* Wg = (const float*)d_in[1];
    const float* Wu = (const float*)d_in[2];
    const float* Wd = (const float*)d_in[3];
    const float* Wr = (const float*)d_in[4];
    float* out = (float*)d_out;

    zero_kernel<<<(out_size + 255) / 256, 256>>>(out, out_size);
    router_kernel<<<NT / 8, 256>>>(x, Wr);
    prefix_kernel<<<1, 32>>>();

    dim3 g1(NH / TN, NT / TM, NE);   // (64, 64, 8)
    gemm1_kernel<<<g1, 256>>>(x, Wg, Wu);

    dim3 g2(DM / TN, NT / TM, NE);   // (16, 64, 8)
    gemm2_kernel<<<g2, 256>>>(Wd, out);
}